// round 9
// baseline (speedup 1.0000x reference)
#include <cuda_runtime.h>
#include <cuda_bf16.h>

#define NA 51   // n_atom

// Scratch for deterministic single-kernel loss reduction (no cudaMalloc allowed).
__device__ float        g_partials[8192];
__device__ unsigned int g_count = 0;

__global__ __launch_bounds__(512, 3) void dtd_kernel(
    const float* __restrict__ dist,          // (B, N, NA)
    const float* __restrict__ next_n_dist,   // (B, N, NA)
    const int*   __restrict__ action,        // (B,)
    const int*   __restrict__ next_n_action, // (B,)
    const float* __restrict__ reward,        // (T, B)
    const unsigned int* __restrict__ done,   // (B,) 32-bit bool encoding
    const float* __restrict__ weight,        // (B,)
    const float* __restrict__ gamma_p,
    const float* __restrict__ vmin_p,
    const float* __restrict__ vmax_p,
    float* __restrict__ out,                 // flattened (loss?, td_err[B])
    int B, int N, int T, int has_loss, int td_off)
{
    __shared__ float s_log[16][4][64];       // per-warp, per-element log p rows
    __shared__ float s_w[16];
    __shared__ int   s_last;

    const int warp = threadIdx.x >> 5;
    const int lane = threadIdx.x & 31;
    const int b0   = blockIdx.x * 64 + warp * 4;   // 4 batch elements per warp
    const unsigned FULL = 0xffffffffu;

    const float gamma  = __ldg(gamma_p);
    const float v_min  = __ldg(vmin_p);
    const float v_max  = __ldg(vmax_p);
    const float inv_dz = (float)(NA - 1) / (v_max - v_min);
    const float fMax   = (float)(NA - 1);

    float* __restrict__ td_out = out + td_off;

    // ---- ALL index loads unconditional and front-batched (parallel chains) ----
    int  bc[4], a[4], na[4];
    bool dn[4];
    #pragma unroll
    for (int i = 0; i < 4; i++) {
        bc[i] = min(b0 + i, B - 1);
        a[i]  = __ldg(&action[bc[i]]);
        na[i] = __ldg(&next_n_action[bc[i]]);
        dn[i] = (__ldg(&done[bc[i]]) != 0u);
    }
    float wlane = 0.0f;
    if (lane < 4) wlane = __ldg(&weight[min(b0 + lane, B - 1)]);

    // ---- n-step return: lanes 0..3 each own one element, then broadcast ----
    float rv = 0.0f;
    {
        const int bl = min(b0 + (lane & 3), B - 1);
        if (lane < 4) {
            float gf = 1.0f;
            for (int t = 0; t < T; t++) {
                rv = fmaf(gf, __ldg(&reward[t * B + bl]), rv);
                gf *= gamma;
            }
        }
    }
    float gT = 1.0f;
    for (int t = 0; t < T; t++) gT *= gamma;

    float r[4];
    #pragma unroll
    for (int i = 0; i < 4; i++) r[i] = __shfl_sync(FULL, rv, i);

    // ---- done-case support index + interpolation fraction (cheap ALU) ----
    int   l_d[4];
    float frac_d[4];
    #pragma unroll
    for (int i = 0; i < 4; i++) {
        float bb  = fminf(fmaxf((r[i] - v_min) * inv_dz, 0.0f), fMax);
        l_d[i]    = max(__float2int_ru(bb) - 1, 0);   // u == l+1 always
        frac_d[i] = bb - (float)l_d[i];
    }

    // ---- row gathers: full rows ONLY for not-done elements (2-level chain) ----
    float plo[4], phi[4], tlo[4], thi[4];
    #pragma unroll
    for (int i = 0; i < 4; i++) {
        plo[i] = 1.0f; phi[i] = 1.0f;
        if (!dn[i]) {                          // dep: action+done loads only
            const unsigned op = (unsigned)(bc[i] * N + a[i]) * NA;
            plo[i] = __ldg(&dist[op + lane]);
            if (lane < NA - 32) phi[i] = __ldg(&dist[op + lane + 32]);
        }
    }
    #pragma unroll
    for (int i = 0; i < 4; i++) {
        tlo[i] = 0.0f; thi[i] = 0.0f;
        if (!dn[i]) {                          // dep: na+done loads only
            const unsigned ot = (unsigned)(bc[i] * N + na[i]) * NA;
            tlo[i] = __ldg(&next_n_dist[ot + lane]);
            if (lane < NA - 32) thi[i] = __ldg(&next_n_dist[ot + lane + 32]);
        }
    }

    // ---- done elements: ONE 8-lane LDG fetches (logp[l], logp[l+1]) x4 ----
    // (3-level chain reward->r->l_d->LDG, overlapped with the full-row chains)
    float dlog;
    {
        int  bce = bc[0], ae = a[0], le = l_d[0];
        bool de  = dn[0];
        const int ii = lane >> 1;              // element owned by this lane pair
        if (ii == 1) { bce = bc[1]; ae = a[1]; le = l_d[1]; de = dn[1]; }
        if (ii == 2) { bce = bc[2]; ae = a[2]; le = l_d[2]; de = dn[2]; }
        if (ii == 3) { bce = bc[3]; ae = a[3]; le = l_d[3]; de = dn[3]; }
        float dv = 1.0f;
        if (lane < 8 && de)
            dv = __ldg(&dist[(unsigned)(bce * N + ae) * NA + (unsigned)le + (lane & 1)]);
        dlog = __logf(dv);   // lanes 2i,2i+1 hold logp[l],logp[l+1] of element i
    }

    // ---- logs into per-warp shared (not-done only; hi-half pad log(1)=0) ----
    #pragma unroll
    for (int i = 0; i < 4; i++) {
        if (!dn[i]) {
            s_log[warp][i][lane]      = __logf(plo[i]);
            s_log[warp][i][lane + 32] = __logf(phi[i]);
        }
    }
    __syncwarp();

    const float jf0 = (float)lane;
    const float jf1 = (float)(lane + 32);

    float acc[4];
    #pragma unroll
    for (int i = 0; i < 4; i++) {
        acc[i] = 0.0f;
        if (!dn[i]) {
            const float* sl = s_log[warp][i];
            // linearized: bb_j = clamp(c + gT*j, 0, NA-1)
            const float c = (fmaf(gT, v_min, r[i]) - v_min) * inv_dz;
            {   // atoms j = lane
                float bb = fminf(fmaxf(fmaf(gT, jf0, c), 0.0f), fMax);
                int   l  = max(__float2int_ru(bb) - 1, 0);
                float fl = (float)l;
                float lo = sl[l], hi = sl[l + 1];
                acc[i] = tlo[i] * fmaf(bb - fl, hi - lo, lo);
            }
            {   // atoms j = lane+32 (thi=0 for lanes >= 19)
                float bb = fminf(fmaxf(fmaf(gT, jf1, c), 0.0f), fMax);
                int   l  = max(__float2int_ru(bb) - 1, 0);
                float fl = (float)l;
                float lo = sl[l], hi = sl[l + 1];
                acc[i] = fmaf(thi[i], fmaf(bb - fl, hi - lo, lo), acc[i]);
            }
        }
    }

    // ---- fused 4-element reduction: element i's total lands in lanes lane&3==i ----
    #pragma unroll
    for (int i = 0; i < 4; i++) {
        acc[i] += __shfl_xor_sync(FULL, acc[i], 1);
        acc[i] += __shfl_xor_sync(FULL, acc[i], 2);
    }
    const int e = lane & 3;
    float v = acc[0];
    if (e == 1) v = acc[1];
    if (e == 2) v = acc[2];
    if (e == 3) v = acc[3];
    v += __shfl_xor_sync(FULL, v, 4);
    v += __shfl_xor_sync(FULL, v, 8);
    v += __shfl_xor_sync(FULL, v, 16);
    float tv = -v;

    // ---- done override: 2-point interpolation from dlog lanes ----
    {
        float lo = __shfl_sync(FULL, dlog, 2 * e);
        float hi = __shfl_sync(FULL, dlog, 2 * e + 1);
        float fe = frac_d[0];
        bool  de = dn[0];
        if (e == 1) { fe = frac_d[1]; de = dn[1]; }
        if (e == 2) { fe = frac_d[2]; de = dn[2]; }
        if (e == 3) { fe = frac_d[3]; de = dn[3]; }
        float tvd = -fmaf(fe, hi - lo, lo);
        if (de) tv = tvd;
    }

    // ---- coalesced td_err store + weighted partial (lanes 0-3) ----
    float ws = 0.0f;
    if (lane < 4 && b0 + lane < B) {
        td_out[b0 + lane] = tv;
        ws = tv * wlane;
    }
    ws += __shfl_xor_sync(FULL, ws, 1);
    ws += __shfl_xor_sync(FULL, ws, 2);
    if (lane == 0) s_w[warp] = ws;
    __syncthreads();

    // ---- block partial + last-block deterministic loss reduction ----
    if (threadIdx.x == 0) {
        float pv = 0.0f;
        #pragma unroll
        for (int w = 0; w < 16; w++) pv += s_w[w];
        g_partials[blockIdx.x] = pv;
        __threadfence();
        unsigned int ticket = atomicAdd(&g_count, 1u);
        s_last = (ticket == gridDim.x - 1) ? 1 : 0;
    }
    __syncthreads();

    if (s_last) {
        __threadfence();
        // Unordered L2 loads (visible after fence+ticket acquire): all issue
        // back-to-back -> ~1 round trip instead of a serialized volatile chain.
        float pv = 0.0f;
        for (int i = threadIdx.x; i < (int)gridDim.x; i += blockDim.x)
            pv += __ldcg(&g_partials[i]);
        #pragma unroll
        for (int o = 16; o; o >>= 1)
            pv += __shfl_xor_sync(FULL, pv, o);
        if (lane == 0) s_w[warp] = pv;
        __syncthreads();
        if (threadIdx.x < 32) {
            pv = (lane < 16) ? s_w[lane] : 0.0f;
            #pragma unroll
            for (int o = 8; o; o >>= 1)
                pv += __shfl_xor_sync(FULL, pv, o);
            if (threadIdx.x == 0) {
                if (has_loss) out[0] = pv * (1.0f / (float)B);
                g_count = 0;                    // reset for next graph replay
            }
        }
    }
}

extern "C" void kernel_launch(void* const* d_in, const int* in_sizes, int n_in,
                              void* d_out, int out_size)
{
    const float*        dist          = (const float*)d_in[0];
    const float*        next_n_dist   = (const float*)d_in[1];
    const int*          action        = (const int*)d_in[2];
    const int*          next_n_action = (const int*)d_in[3];
    const float*        reward        = (const float*)d_in[4];
    const unsigned int* done          = (const unsigned int*)d_in[5];
    const float*        weight        = (const float*)d_in[6];
    const float*        gamma_p       = (const float*)d_in[7];
    const float*        vmin_p        = (const float*)d_in[8];
    const float*        vmax_p        = (const float*)d_in[9];

    const int B = in_sizes[2];                 // action is (B,)
    const int N = in_sizes[0] / (B * NA);      // dist is (B, N, NA)
    const int T = in_sizes[4] / B;             // reward is (T, B)

    float* out = (float*)d_out;
    const int td_off   = out_size - B;         // td_err is the trailing B elements
    const int has_loss = (out_size > B) ? 1 : 0;

    const int blocks = (B + 63) / 64;          // 64 batch elements per 512-thread block
    dtd_kernel<<<blocks, 512>>>(dist, next_n_dist, action, next_n_action,
                                reward, done, weight, gamma_p, vmin_p, vmax_p,
                                out, B, N, T, has_loss, td_off);
}

// round 10
// speedup vs baseline: 1.1157x; 1.1157x over previous
#include <cuda_runtime.h>
#include <cuda_bf16.h>

#define NA 51   // n_atom

// Scratch for deterministic single-kernel loss reduction (no cudaMalloc allowed).
__device__ float        g_partials[8192];
__device__ unsigned int g_count = 0;

__global__ __launch_bounds__(256) void dtd_kernel(
    const float* __restrict__ dist,          // (B, N, NA)
    const float* __restrict__ next_n_dist,   // (B, N, NA)
    const int*   __restrict__ action,        // (B,)
    const int*   __restrict__ next_n_action, // (B,)
    const float* __restrict__ reward,        // (T, B)
    const unsigned int* __restrict__ done,   // (B,) 32-bit bool encoding
    const float* __restrict__ weight,        // (B,)
    const float* __restrict__ gamma_p,
    const float* __restrict__ vmin_p,
    const float* __restrict__ vmax_p,
    float* __restrict__ out,                 // flattened (loss?, td_err[B])
    int B, int N, int T, int has_loss, int td_off)
{
    __shared__ float s_log[8][4][64];        // per-warp, per-element log p rows
    __shared__ float s_w[8];
    __shared__ int   s_last;

    const int warp = threadIdx.x >> 5;
    const int lane = threadIdx.x & 31;
    const int b0   = blockIdx.x * 32 + warp * 4;   // 4 batch elements per warp
    const unsigned FULL = 0xffffffffu;

    const float gamma  = __ldg(gamma_p);
    const float v_min  = __ldg(vmin_p);
    const float v_max  = __ldg(vmax_p);
    const float inv_dz = (float)(NA - 1) / (v_max - v_min);
    const float fMax   = (float)(NA - 1);

    float* __restrict__ td_out = out + td_off;

    // ---- scalar per-element loads (broadcast, warp-uniform per i) ----
    int  bc[4], a[4], na[4];
    bool dn[4];
    #pragma unroll
    for (int i = 0; i < 4; i++) {
        bc[i] = min(b0 + i, B - 1);
        a[i]  = __ldg(&action[bc[i]]);
        na[i] = __ldg(&next_n_action[bc[i]]);
        dn[i] = (__ldg(&done[bc[i]]) != 0u);
    }
    float wlane = 0.0f;
    if (lane < 4) wlane = __ldg(&weight[min(b0 + lane, B - 1)]);

    // ---- n-step return: lanes 0..3 each own one element, then broadcast ----
    float rv = 0.0f;
    {
        const int bl = min(b0 + (lane & 3), B - 1);
        if (lane < 4) {
            float gf = 1.0f;
            for (int t = 0; t < T; t++) {
                rv = fmaf(gf, __ldg(&reward[t * B + bl]), rv);
                gf *= gamma;
            }
        }
    }
    float gT = 1.0f;
    for (int t = 0; t < T; t++) gT *= gamma;

    float r[4];
    #pragma unroll
    for (int i = 0; i < 4; i++) r[i] = __shfl_sync(FULL, rv, i);

    // ---- front-batched row gathers (.cg: L1 is flushed per launch; these are
    //      single-use random rows that hit L2 on graph replay) ----
    float plo[4], phi[4], tlo[4], thi[4];
    #pragma unroll
    for (int i = 0; i < 4; i++) {
        const unsigned op = (unsigned)(bc[i] * N + a[i]) * NA;
        plo[i] = __ldcg(&dist[op + lane]);
        phi[i] = (lane < NA - 32) ? __ldcg(&dist[op + lane + 32]) : 1.0f;
    }
    #pragma unroll
    for (int i = 0; i < 4; i++) {
        tlo[i] = 0.0f; thi[i] = 0.0f;
        if (!dn[i]) {                          // warp-uniform branch
            const unsigned ot = (unsigned)(bc[i] * N + na[i]) * NA;
            tlo[i] = __ldcg(&next_n_dist[ot + lane]);
            if (lane < NA - 32) thi[i] = __ldcg(&next_n_dist[ot + lane + 32]);
        }
    }

    // ---- logs into per-warp shared (hi half unconditional: log(1)=0 pad) ----
    #pragma unroll
    for (int i = 0; i < 4; i++) {
        s_log[warp][i][lane]      = __logf(plo[i]);
        s_log[warp][i][lane + 32] = __logf(phi[i]);
    }
    __syncwarp();

    const float jf0 = (float)lane;
    const float jf1 = (float)(lane + 32);

    float acc[4], dval[4];
    #pragma unroll
    for (int i = 0; i < 4; i++) {
        const float* sl = s_log[warp][i];
        acc[i] = 0.0f; dval[i] = 0.0f;
        if (dn[i]) {
            // target_z identical across atoms; sum(td)=1 -> one interpolation
            float bb = fminf(fmaxf((r[i] - v_min) * inv_dz, 0.0f), fMax);
            int   l  = max(__float2int_ru(bb) - 1, 0);
            float fl = (float)l;
            float lo = sl[l], hi = sl[l + 1];
            dval[i] = -fmaf(bb - fl, hi - lo, lo);
        } else {
            // linearized: bb_j = clamp(c + gT*j, 0, NA-1)
            const float c = (fmaf(gT, v_min, r[i]) - v_min) * inv_dz;
            {   // atoms j = lane
                float bb = fminf(fmaxf(fmaf(gT, jf0, c), 0.0f), fMax);
                int   l  = max(__float2int_ru(bb) - 1, 0);
                float fl = (float)l;
                float lo = sl[l], hi = sl[l + 1];
                acc[i] = tlo[i] * fmaf(bb - fl, hi - lo, lo);
            }
            {   // atoms j = lane+32 (thi=0 for lanes >= 19)
                float bb = fminf(fmaxf(fmaf(gT, jf1, c), 0.0f), fMax);
                int   l  = max(__float2int_ru(bb) - 1, 0);
                float fl = (float)l;
                float lo = sl[l], hi = sl[l + 1];
                acc[i] = fmaf(thi[i], fmaf(bb - fl, hi - lo, lo), acc[i]);
            }
        }
    }

    // ---- fused 4-element reduction: element i's total lands in lanes lane&3==i ----
    #pragma unroll
    for (int i = 0; i < 4; i++) {
        acc[i] += __shfl_xor_sync(FULL, acc[i], 1);
        acc[i] += __shfl_xor_sync(FULL, acc[i], 2);
    }
    const int e = lane & 3;
    float v = acc[0];
    if (e == 1) v = acc[1];
    if (e == 2) v = acc[2];
    if (e == 3) v = acc[3];
    v += __shfl_xor_sync(FULL, v, 4);
    v += __shfl_xor_sync(FULL, v, 8);
    v += __shfl_xor_sync(FULL, v, 16);
    float tv = -v;
    if (e == 0 && dn[0]) tv = dval[0];
    if (e == 1 && dn[1]) tv = dval[1];
    if (e == 2 && dn[2]) tv = dval[2];
    if (e == 3 && dn[3]) tv = dval[3];

    // ---- coalesced td_err store + weighted partial (lanes 0-3) ----
    float ws = 0.0f;
    if (lane < 4 && b0 + lane < B) {
        td_out[b0 + lane] = tv;
        ws = tv * wlane;
    }
    ws += __shfl_xor_sync(FULL, ws, 1);
    ws += __shfl_xor_sync(FULL, ws, 2);
    if (lane == 0) s_w[warp] = ws;
    __syncthreads();

    // ---- block partial + last-block deterministic loss reduction ----
    if (threadIdx.x == 0) {
        float pv = 0.0f;
        #pragma unroll
        for (int w = 0; w < 8; w++) pv += s_w[w];
        g_partials[blockIdx.x] = pv;
        __threadfence();
        unsigned int ticket = atomicAdd(&g_count, 1u);
        s_last = (ticket == gridDim.x - 1) ? 1 : 0;
    }
    __syncthreads();

    if (s_last) {
        __threadfence();
        // Unordered vectorized L2 loads (visible after fence+ticket acquire):
        // all issue back-to-back -> ~1 round trip, no serialized volatile chain.
        float pv = 0.0f;
        const int nq = (int)gridDim.x >> 2;             // gridDim multiple of 4
        const float4* gp4 = (const float4*)g_partials;
        for (int i = threadIdx.x; i < nq; i += blockDim.x) {
            float4 q = __ldcg(&gp4[i]);
            pv += (q.x + q.y) + (q.z + q.w);
        }
        for (int i = (nq << 2) + threadIdx.x; i < (int)gridDim.x; i += blockDim.x)
            pv += __ldcg(&g_partials[i]);
        #pragma unroll
        for (int o = 16; o; o >>= 1)
            pv += __shfl_xor_sync(FULL, pv, o);
        if (lane == 0) s_w[warp] = pv;
        __syncthreads();
        if (threadIdx.x < 32) {
            pv = (lane < 8) ? s_w[lane] : 0.0f;
            #pragma unroll
            for (int o = 4; o; o >>= 1)
                pv += __shfl_xor_sync(FULL, pv, o);
            if (threadIdx.x == 0) {
                if (has_loss) out[0] = pv * (1.0f / (float)B);
                g_count = 0;                    // reset for next graph replay
            }
        }
    }
}

extern "C" void kernel_launch(void* const* d_in, const int* in_sizes, int n_in,
                              void* d_out, int out_size)
{
    const float*        dist          = (const float*)d_in[0];
    const float*        next_n_dist   = (const float*)d_in[1];
    const int*          action        = (const int*)d_in[2];
    const int*          next_n_action = (const int*)d_in[3];
    const float*        reward        = (const float*)d_in[4];
    const unsigned int* done          = (const unsigned int*)d_in[5];
    const float*        weight        = (const float*)d_in[6];
    const float*        gamma_p       = (const float*)d_in[7];
    const float*        vmin_p        = (const float*)d_in[8];
    const float*        vmax_p        = (const float*)d_in[9];

    const int B = in_sizes[2];                 // action is (B,)
    const int N = in_sizes[0] / (B * NA);      // dist is (B, N, NA)
    const int T = in_sizes[4] / B;             // reward is (T, B)

    float* out = (float*)d_out;
    const int td_off   = out_size - B;         // td_err is the trailing B elements
    const int has_loss = (out_size > B) ? 1 : 0;

    const int blocks = (B + 31) / 32;          // 32 batch elements per 256-thread block
    dtd_kernel<<<blocks, 256>>>(dist, next_n_dist, action, next_n_action,
                                reward, done, weight, gamma_p, vmin_p, vmax_p,
                                out, B, N, T, has_loss, td_off);
}

// round 11
// speedup vs baseline: 1.1326x; 1.0152x over previous
#include <cuda_runtime.h>
#include <cuda_bf16.h>

#define NA 51   // n_atom

// Scratch for deterministic single-kernel loss reduction (no cudaMalloc allowed).
__device__ float        g_partials[8192];
__device__ unsigned int g_count = 0;

__global__ __launch_bounds__(512) void dtd_kernel(
    const float* __restrict__ dist,          // (B, N, NA)
    const float* __restrict__ next_n_dist,   // (B, N, NA)
    const int*   __restrict__ action,        // (B,)
    const int*   __restrict__ next_n_action, // (B,)
    const float* __restrict__ reward,        // (T, B)
    const unsigned int* __restrict__ done,   // (B,) 32-bit bool encoding
    const float* __restrict__ weight,        // (B,)
    const float* __restrict__ gamma_p,
    const float* __restrict__ vmin_p,
    const float* __restrict__ vmax_p,
    float* __restrict__ out,                 // flattened (loss?, td_err[B])
    int B, int N, int T, int has_loss, int td_off)
{
    __shared__ float s_log[16][8][64];       // per-warp, per-element log p rows
    __shared__ float s_w[16];
    __shared__ int   s_last;

    const int warp = threadIdx.x >> 5;
    const int lane = threadIdx.x & 31;
    const int b0   = blockIdx.x * 128 + warp * 8;  // 8 batch elements per warp
    const unsigned FULL = 0xffffffffu;

    const float gamma  = __ldg(gamma_p);
    const float v_min  = __ldg(vmin_p);
    const float v_max  = __ldg(vmax_p);
    const float inv_dz = (float)(NA - 1) / (v_max - v_min);
    const float fMax   = (float)(NA - 1);

    float* __restrict__ td_out = out + td_off;

    // ---- scalar per-element loads (broadcast, warp-uniform per i) ----
    unsigned op[8], ot[8];
    bool dn[8];
    #pragma unroll
    for (int i = 0; i < 8; i++) {
        const int bcd = min(b0 + i, B - 1);
        const int ai  = __ldg(&action[bcd]);
        const int nai = __ldg(&next_n_action[bcd]);
        dn[i] = (__ldg(&done[bcd]) != 0u);
        op[i] = (unsigned)(bcd * N + ai)  * NA;
        ot[i] = (unsigned)(bcd * N + nai) * NA;
    }
    float wlane = 0.0f;
    if (lane < 8) wlane = __ldg(&weight[min(b0 + lane, B - 1)]);

    // ---- n-step return: lanes 0..7 each own one element, then broadcast ----
    float rv = 0.0f;
    {
        const int bl = min(b0 + (lane & 7), B - 1);
        if (lane < 8) {
            float gf = 1.0f;
            for (int t = 0; t < T; t++) {
                rv = fmaf(gf, __ldg(&reward[t * B + bl]), rv);
                gf *= gamma;
            }
        }
    }
    float gT = 1.0f;
    for (int t = 0; t < T; t++) gT *= gamma;

    float r[8];
    #pragma unroll
    for (int i = 0; i < 8; i++) r[i] = __shfl_sync(FULL, rv, i);

    // ---- front-batched row gathers: all 32 LDGs issued before any use ----
    float plo[8], phi[8], tlo[8], thi[8];
    #pragma unroll
    for (int i = 0; i < 8; i++) {
        plo[i] = __ldg(&dist[op[i] + lane]);
        phi[i] = (lane < NA - 32) ? __ldg(&dist[op[i] + lane + 32]) : 1.0f;
    }
    #pragma unroll
    for (int i = 0; i < 8; i++) {
        tlo[i] = 0.0f; thi[i] = 0.0f;
        if (!dn[i]) {                          // warp-uniform branch
            tlo[i] = __ldg(&next_n_dist[ot[i] + lane]);
            if (lane < NA - 32) thi[i] = __ldg(&next_n_dist[ot[i] + lane + 32]);
        }
    }

    // ---- logs into per-warp shared (hi half unconditional: log(1)=0 pad) ----
    #pragma unroll
    for (int i = 0; i < 8; i++) {
        s_log[warp][i][lane]      = __logf(plo[i]);
        s_log[warp][i][lane + 32] = __logf(phi[i]);
    }
    __syncwarp();

    const float jf0 = (float)lane;
    const float jf1 = (float)(lane + 32);

    float acc[8], dval[8];
    #pragma unroll
    for (int i = 0; i < 8; i++) {
        const float* sl = s_log[warp][i];
        acc[i] = 0.0f; dval[i] = 0.0f;
        if (dn[i]) {
            // target_z identical across atoms; sum(td)=1 -> one interpolation
            float bb = fminf(fmaxf((r[i] - v_min) * inv_dz, 0.0f), fMax);
            int   l  = max(__float2int_ru(bb) - 1, 0);
            float fl = (float)l;
            float lo = sl[l], hi = sl[l + 1];
            dval[i] = -fmaf(bb - fl, hi - lo, lo);
        } else {
            // linearized: bb_j = clamp(c + gT*j, 0, NA-1)
            const float c = (fmaf(gT, v_min, r[i]) - v_min) * inv_dz;
            {   // atoms j = lane
                float bb = fminf(fmaxf(fmaf(gT, jf0, c), 0.0f), fMax);
                int   l  = max(__float2int_ru(bb) - 1, 0);
                float fl = (float)l;
                float lo = sl[l], hi = sl[l + 1];
                acc[i] = tlo[i] * fmaf(bb - fl, hi - lo, lo);
            }
            {   // atoms j = lane+32 (thi=0 for lanes >= 19)
                float bb = fminf(fmaxf(fmaf(gT, jf1, c), 0.0f), fMax);
                int   l  = max(__float2int_ru(bb) - 1, 0);
                float fl = (float)l;
                float lo = sl[l], hi = sl[l + 1];
                acc[i] = fmaf(thi[i], fmaf(bb - fl, hi - lo, lo), acc[i]);
            }
        }
    }

    // ---- fused reductions: group A (elems 0-3) -> lanes e=lane&3,
    //      group B (elems 4-7) -> same mapping; stores use lanes 0-7 ----
    #pragma unroll
    for (int i = 0; i < 8; i++) {
        acc[i] += __shfl_xor_sync(FULL, acc[i], 1);
        acc[i] += __shfl_xor_sync(FULL, acc[i], 2);
    }
    const int e = lane & 3;
    float vA = acc[0], vB = acc[4];
    if (e == 1) { vA = acc[1]; vB = acc[5]; }
    if (e == 2) { vA = acc[2]; vB = acc[6]; }
    if (e == 3) { vA = acc[3]; vB = acc[7]; }
    vA += __shfl_xor_sync(FULL, vA, 4);
    vA += __shfl_xor_sync(FULL, vA, 8);
    vA += __shfl_xor_sync(FULL, vA, 16);
    vB += __shfl_xor_sync(FULL, vB, 4);
    vB += __shfl_xor_sync(FULL, vB, 8);
    vB += __shfl_xor_sync(FULL, vB, 16);
    float tvA = -vA, tvB = -vB;
    if (e == 0) { if (dn[0]) tvA = dval[0]; if (dn[4]) tvB = dval[4]; }
    if (e == 1) { if (dn[1]) tvA = dval[1]; if (dn[5]) tvB = dval[5]; }
    if (e == 2) { if (dn[2]) tvA = dval[2]; if (dn[6]) tvB = dval[6]; }
    if (e == 3) { if (dn[3]) tvA = dval[3]; if (dn[7]) tvB = dval[7]; }

    // lanes 0-3 hold elements 0-3 in tvA; lanes 4-7 hold elements 4-7 in tvB
    float tv = (lane < 4) ? tvA : tvB;
    float ws = 0.0f;
    if (lane < 8 && b0 + lane < B) {
        td_out[b0 + lane] = tv;
        ws = tv * wlane;
    }
    ws += __shfl_xor_sync(FULL, ws, 1);
    ws += __shfl_xor_sync(FULL, ws, 2);
    ws += __shfl_xor_sync(FULL, ws, 4);
    if (lane == 0) s_w[warp] = ws;
    __syncthreads();

    // ---- block partial + last-block deterministic loss reduction ----
    if (threadIdx.x == 0) {
        float pv = 0.0f;
        #pragma unroll
        for (int w = 0; w < 16; w++) pv += s_w[w];
        g_partials[blockIdx.x] = pv;
        __threadfence();
        unsigned int ticket = atomicAdd(&g_count, 1u);
        s_last = (ticket == gridDim.x - 1) ? 1 : 0;
    }
    __syncthreads();

    if (s_last) {
        __threadfence();
        // Unordered vectorized L2 loads (visible after fence+ticket acquire).
        float pv = 0.0f;
        const int nq = (int)gridDim.x >> 2;
        const float4* gp4 = (const float4*)g_partials;
        for (int i = threadIdx.x; i < nq; i += blockDim.x) {
            float4 q = __ldcg(&gp4[i]);
            pv += (q.x + q.y) + (q.z + q.w);
        }
        for (int i = (nq << 2) + threadIdx.x; i < (int)gridDim.x; i += blockDim.x)
            pv += __ldcg(&g_partials[i]);
        #pragma unroll
        for (int o = 16; o; o >>= 1)
            pv += __shfl_xor_sync(FULL, pv, o);
        if (lane == 0) s_w[warp] = pv;
        __syncthreads();
        if (threadIdx.x < 32) {
            pv = (lane < 16) ? s_w[lane] : 0.0f;
            #pragma unroll
            for (int o = 8; o; o >>= 1)
                pv += __shfl_xor_sync(FULL, pv, o);
            if (threadIdx.x == 0) {
                if (has_loss) out[0] = pv * (1.0f / (float)B);
                g_count = 0;                    // reset for next graph replay
            }
        }
    }
}

extern "C" void kernel_launch(void* const* d_in, const int* in_sizes, int n_in,
                              void* d_out, int out_size)
{
    const float*        dist          = (const float*)d_in[0];
    const float*        next_n_dist   = (const float*)d_in[1];
    const int*          action        = (const int*)d_in[2];
    const int*          next_n_action = (const int*)d_in[3];
    const float*        reward        = (const float*)d_in[4];
    const unsigned int* done          = (const unsigned int*)d_in[5];
    const float*        weight        = (const float*)d_in[6];
    const float*        gamma_p       = (const float*)d_in[7];
    const float*        vmin_p        = (const float*)d_in[8];
    const float*        vmax_p        = (const float*)d_in[9];

    const int B = in_sizes[2];                 // action is (B,)
    const int N = in_sizes[0] / (B * NA);      // dist is (B, N, NA)
    const int T = in_sizes[4] / B;             // reward is (T, B)

    float* out = (float*)d_out;
    const int td_off   = out_size - B;         // td_err is the trailing B elements
    const int has_loss = (out_size > B) ? 1 : 0;

    const int blocks = (B + 127) / 128;        // 128 batch elements per 512-thread block
    dtd_kernel<<<blocks, 512>>>(dist, next_n_dist, action, next_n_action,
                                reward, done, weight, gamma_p, vmin_p, vmax_p,
                                out, B, N, T, has_loss, td_off);
}

// round 12
// speedup vs baseline: 1.2696x; 1.1210x over previous
#include <cuda_runtime.h>
#include <cuda_bf16.h>

#define NA 51   // n_atom

// Scratch for deterministic single-kernel loss reduction (no cudaMalloc allowed).
__device__ float        g_partials[8192];
__device__ unsigned int g_count = 0;

struct RowBuf { float plo[4], phi[4], tlo[4], thi[4]; };

__global__ __launch_bounds__(256) void dtd_kernel(
    const float* __restrict__ dist,          // (B, N, NA)
    const float* __restrict__ next_n_dist,   // (B, N, NA)
    const int*   __restrict__ action,        // (B,)
    const int*   __restrict__ next_n_action, // (B,)
    const float* __restrict__ reward,        // (T, B)
    const unsigned int* __restrict__ done,   // (B,) 32-bit bool encoding
    const float* __restrict__ weight,        // (B,)
    const float* __restrict__ gamma_p,
    const float* __restrict__ vmin_p,
    const float* __restrict__ vmax_p,
    float* __restrict__ out,                 // flattened (loss?, td_err[B])
    int B, int N, int T, int has_loss, int td_off)
{
    __shared__ float    s_log[8][4][64];     // per-warp scratch, reused per group
    __shared__ unsigned s_off[8][32];        // [0:16) dist row off, [16:32) next row off
    __shared__ float    s_w[8];
    __shared__ int      s_last;

    const int warp = threadIdx.x >> 5;
    const int lane = threadIdx.x & 31;
    const int b0   = blockIdx.x * 128 + warp * 16;  // 16 batch elements per warp
    const unsigned FULL = 0xffffffffu;

    const float gamma  = __ldg(gamma_p);
    const float v_min  = __ldg(vmin_p);
    const float v_max  = __ldg(vmax_p);
    const float inv_dz = (float)(NA - 1) / (v_max - v_min);
    const float fMax   = (float)(NA - 1);

    float* __restrict__ td_out = out + td_off;

    // ---- idx phase: 3 wide LDGs cover all 16 elements' metadata ----
    const int el  = lane & 15;
    const int bce = min(b0 + el, B - 1);
    int idx = (lane < 16) ? __ldg(&action[bce]) : __ldg(&next_n_action[bce]);
    unsigned dmask;
    {
        unsigned dv = (lane < 16) ? __ldg(&done[bce]) : 0u;
        dmask = __ballot_sync(FULL, dv != 0u) & 0xffffu;   // uniform 16-bit done mask
    }
    s_off[warp][lane] = (unsigned)(bce * N + idx) * NA;

    float wlane = 0.0f;
    float rv    = 0.0f;
    if (lane < 16) {
        wlane = __ldg(&weight[bce]);
        float gf = 1.0f;
        for (int t = 0; t < T; t++) {
            rv = fmaf(gf, __ldg(&reward[t * B + bce]), rv);
            gf *= gamma;
        }
    }
    float gT = 1.0f;
    for (int t = 0; t < T; t++) gT *= gamma;
    __syncwarp();

    const float jf0 = (float)lane;
    const float jf1 = (float)(lane + 32);
    float tv = 0.0f;

    // ---- pipeline helpers ----
    auto load_group = [&](int g, RowBuf& rb) {
        #pragma unroll
        for (int i = 0; i < 4; i++) {
            const unsigned op = s_off[warp][g * 4 + i];
            rb.plo[i] = __ldg(&dist[op + lane]);
            rb.phi[i] = (lane < NA - 32) ? __ldg(&dist[op + lane + 32]) : 1.0f;
        }
        #pragma unroll
        for (int i = 0; i < 4; i++) {
            rb.tlo[i] = 0.0f; rb.thi[i] = 0.0f;
            if (!((dmask >> (g * 4 + i)) & 1u)) {        // warp-uniform
                const unsigned ot = s_off[warp][16 + g * 4 + i];
                rb.tlo[i] = __ldg(&next_n_dist[ot + lane]);
                if (lane < NA - 32) rb.thi[i] = __ldg(&next_n_dist[ot + lane + 32]);
            }
        }
    };

    auto compute_group = [&](int g, RowBuf& rb) {
        #pragma unroll
        for (int i = 0; i < 4; i++) {
            s_log[warp][i][lane]      = __logf(rb.plo[i]);
            s_log[warp][i][lane + 32] = __logf(rb.phi[i]);
        }
        __syncwarp();
        float acc[4], dval[4];
        #pragma unroll
        for (int i = 0; i < 4; i++) {
            const float* sl = s_log[warp][i];
            const float ri  = __shfl_sync(FULL, rv, g * 4 + i);
            const bool  dni = (dmask >> (g * 4 + i)) & 1u;
            acc[i] = 0.0f; dval[i] = 0.0f;
            if (dni) {
                // target_z identical across atoms; sum(td)=1 -> one interpolation
                float bb = fminf(fmaxf((ri - v_min) * inv_dz, 0.0f), fMax);
                int   l  = max(__float2int_ru(bb) - 1, 0);
                float fl = (float)l;
                float lo = sl[l], hi = sl[l + 1];
                dval[i] = -fmaf(bb - fl, hi - lo, lo);
            } else {
                // linearized: bb_j = clamp(c + gT*j, 0, NA-1)
                const float c = (fmaf(gT, v_min, ri) - v_min) * inv_dz;
                {   // atoms j = lane
                    float bb = fminf(fmaxf(fmaf(gT, jf0, c), 0.0f), fMax);
                    int   l  = max(__float2int_ru(bb) - 1, 0);
                    float fl = (float)l;
                    float lo = sl[l], hi = sl[l + 1];
                    acc[i] = rb.tlo[i] * fmaf(bb - fl, hi - lo, lo);
                }
                {   // atoms j = lane+32 (thi=0 for lanes >= 19)
                    float bb = fminf(fmaxf(fmaf(gT, jf1, c), 0.0f), fMax);
                    int   l  = max(__float2int_ru(bb) - 1, 0);
                    float fl = (float)l;
                    float lo = sl[l], hi = sl[l + 1];
                    acc[i] = fmaf(rb.thi[i], fmaf(bb - fl, hi - lo, lo), acc[i]);
                }
            }
        }
        #pragma unroll
        for (int i = 0; i < 4; i++) {
            acc[i] += __shfl_xor_sync(FULL, acc[i], 1);
            acc[i] += __shfl_xor_sync(FULL, acc[i], 2);
        }
        const int e = lane & 3;
        float v = acc[0];
        if (e == 1) v = acc[1];
        if (e == 2) v = acc[2];
        if (e == 3) v = acc[3];
        v += __shfl_xor_sync(FULL, v, 4);
        v += __shfl_xor_sync(FULL, v, 8);
        v += __shfl_xor_sync(FULL, v, 16);
        float res = -v;
        float dsel = dval[0];
        if (e == 1) dsel = dval[1];
        if (e == 2) dsel = dval[2];
        if (e == 3) dsel = dval[3];
        if ((dmask >> (g * 4 + e)) & 1u) res = dsel;
        if ((lane >> 2) == g) tv = res;   // element g*4+e lands in lane g*4+e
        __syncwarp();                     // protect s_log reuse by next group
    };

    // ---- depth-2 software pipeline over 4 groups ----
    RowBuf A, Bb;
    load_group(0, A);
    load_group(1, Bb);
    compute_group(0, A);
    load_group(2, A);
    compute_group(1, Bb);
    load_group(3, Bb);
    compute_group(2, A);
    compute_group(3, Bb);

    // ---- coalesced td_err store (lanes 0-15) + weighted partial ----
    float ws = 0.0f;
    if (lane < 16 && b0 + lane < B) {
        td_out[b0 + lane] = tv;
        ws = tv * wlane;
    }
    ws += __shfl_xor_sync(FULL, ws, 1);
    ws += __shfl_xor_sync(FULL, ws, 2);
    ws += __shfl_xor_sync(FULL, ws, 4);
    ws += __shfl_xor_sync(FULL, ws, 8);
    if (lane == 0) s_w[warp] = ws;
    __syncthreads();

    // ---- block partial + last-block deterministic loss reduction ----
    if (threadIdx.x == 0) {
        float pv = 0.0f;
        #pragma unroll
        for (int w = 0; w < 8; w++) pv += s_w[w];
        g_partials[blockIdx.x] = pv;
        __threadfence();
        unsigned int ticket = atomicAdd(&g_count, 1u);
        s_last = (ticket == gridDim.x - 1) ? 1 : 0;
    }
    __syncthreads();

    if (s_last) {
        __threadfence();
        // Unordered vectorized L2 loads (visible after fence+ticket acquire).
        float pv = 0.0f;
        const int nq = (int)gridDim.x >> 2;
        const float4* gp4 = (const float4*)g_partials;
        for (int i = threadIdx.x; i < nq; i += blockDim.x) {
            float4 q = __ldcg(&gp4[i]);
            pv += (q.x + q.y) + (q.z + q.w);
        }
        for (int i = (nq << 2) + threadIdx.x; i < (int)gridDim.x; i += blockDim.x)
            pv += __ldcg(&g_partials[i]);
        #pragma unroll
        for (int o = 16; o; o >>= 1)
            pv += __shfl_xor_sync(FULL, pv, o);
        if (lane == 0) s_w[warp] = pv;
        __syncthreads();
        if (threadIdx.x < 32) {
            pv = (lane < 8) ? s_w[lane] : 0.0f;
            #pragma unroll
            for (int o = 4; o; o >>= 1)
                pv += __shfl_xor_sync(FULL, pv, o);
            if (threadIdx.x == 0) {
                if (has_loss) out[0] = pv * (1.0f / (float)B);
                g_count = 0;                    // reset for next graph replay
            }
        }
    }
}

extern "C" void kernel_launch(void* const* d_in, const int* in_sizes, int n_in,
                              void* d_out, int out_size)
{
    const float*        dist          = (const float*)d_in[0];
    const float*        next_n_dist   = (const float*)d_in[1];
    const int*          action        = (const int*)d_in[2];
    const int*          next_n_action = (const int*)d_in[3];
    const float*        reward        = (const float*)d_in[4];
    const unsigned int* done          = (const unsigned int*)d_in[5];
    const float*        weight        = (const float*)d_in[6];
    const float*        gamma_p       = (const float*)d_in[7];
    const float*        vmin_p        = (const float*)d_in[8];
    const float*        vmax_p        = (const float*)d_in[9];

    const int B = in_sizes[2];                 // action is (B,)
    const int N = in_sizes[0] / (B * NA);      // dist is (B, N, NA)
    const int T = in_sizes[4] / B;             // reward is (T, B)

    float* out = (float*)d_out;
    const int td_off   = out_size - B;         // td_err is the trailing B elements
    const int has_loss = (out_size > B) ? 1 : 0;

    const int blocks = (B + 127) / 128;        // 128 batch elements per 256-thread block
    dtd_kernel<<<blocks, 256>>>(dist, next_n_dist, action, next_n_action,
                                reward, done, weight, gamma_p, vmin_p, vmax_p,
                                out, B, N, T, has_loss, td_off);
}